// round 8
// baseline (speedup 1.0000x reference)
#include <cuda_runtime.h>
#include <cstdint>

#define NTHREADS 256
#define HALF_T   128
#define ROWLEN   4096
#define KSEL     8
#define POOL_CAP 128

typedef unsigned long long u64;

// Monotone bijection float -> uint32 (order preserving)
__device__ __forceinline__ unsigned fflip(float f) {
    unsigned u = __float_as_uint(f);
    return (u & 0x80000000u) ? ~u : (u | 0x80000000u);
}
__device__ __forceinline__ float funflip(unsigned u) {
    return __uint_as_float((u & 0x80000000u) ? (u ^ 0x80000000u) : ~u);
}

__device__ __forceinline__ void push_cand(float x, float thr, int idx,
                                          int* cnt, u64* pool) {
    if (x >= thr) {
        int pos = atomicAdd(cnt, 1);
        if (pos < POOL_CAP)
            pool[pos] = ((u64)fflip(x) << 12) | (unsigned)(4095 - idx);
    }
}

__global__ __launch_bounds__(NTHREADS) void kmax_kernel(const float* __restrict__ in,
                                                        float* __restrict__ out) {
    __shared__ unsigned s_m[8];           // per-warp m2 (flipped); warps 0-3 row A, 4-7 row B
    __shared__ int s_cnt[2];
    __shared__ u64 s_pool[2][POOL_CAP];

    const int t = threadIdx.x;
    const int lane = t & 31;
    const int wid = t >> 5;
    const int half = t >> 7;              // 0 = row A, 1 = row B
    const int th = t & (HALF_T - 1);      // thread index within half
    const size_t row = (size_t)blockIdx.x * 2 + half;
    const float4* rp = reinterpret_cast<const float4*>(in + row * (size_t)ROWLEN);

    // Front-batched streaming loads: 8x LDG.128 per thread, all before any sync.
    float4 v[8];
#pragma unroll
    for (int i = 0; i < 8; i++)
        v[i] = __ldcs(rp + i * HALF_T + th);

    if (th == 0) s_cnt[half] = 0;

    // Per-thread max over its 32 elements.
    float gm = fmaxf(fmaxf(v[0].x, v[0].y), fmaxf(v[0].z, v[0].w));
#pragma unroll
    for (int i = 1; i < 8; i++)
        gm = fmaxf(gm, fmaxf(fmaxf(v[i].x, v[i].y), fmaxf(v[i].z, v[i].w)));
    const float gmax = gm;
    const unsigned gx = fflip(gmax);

    // Warp top-2 distinct thread-maxes via hardware REDUX. m1/m2 holders are
    // different threads -> each warp certifies >=2 distinct elements >= m2.
    unsigned m1 = __reduce_max_sync(0xffffffffu, gx);
    unsigned m2 = __reduce_max_sync(0xffffffffu, (gx == m1) ? 0u : gx);
    if (lane == 0) s_m[wid] = m2;
    __syncthreads();

    // Per-half threshold T = MIN over that half's 4 warp m2 values.
    // Safety: 4 warps x >=2 distinct elements >= T -> >=8 elements >= T in the
    // row -> every true top-8 element satisfies x >= T (superset filter).
    const int mb = half * 4;
    unsigned tf = min(min(s_m[mb], s_m[mb + 1]), min(s_m[mb + 2], s_m[mb + 3]));
    const float thr = funflip(tf);

    // Push candidate ELEMENTS (x >= thr) into this half's pool (~8-15 typical).
    if (gmax >= thr) {
#pragma unroll
        for (int c = 0; c < 8; c++) {
            int ib = c * 512 + 4 * th;
            push_cand(v[c].x, thr, ib + 0, &s_cnt[half], s_pool[half]);
            push_cand(v[c].y, thr, ib + 1, &s_cnt[half], s_pool[half]);
            push_cand(v[c].z, thr, ib + 2, &s_cnt[half], s_pool[half]);
            push_cand(v[c].w, thr, ib + 3, &s_cnt[half], s_pool[half]);
        }
    }
    __syncthreads();

    // Parallel extraction: warp 0 handles row A, warp 4 handles row B.
    if ((wid & 3) == 0) {
        const int h = wid >> 2;
        u64* pool = s_pool[h];
        const int n = min(s_cnt[h], POOL_CAP);
        const size_t orow = (size_t)blockIdx.x * 2 + h;

        if (n <= 32) {
            // FAST PATH: one 32-lane bitonic sort of the zero-padded pool.
            u64 key = (lane < n) ? pool[lane] : 0ull;   // keys unique & nonzero
#pragma unroll
            for (int k = 2; k <= 32; k <<= 1) {
#pragma unroll
                for (int j = k >> 1; j > 0; j >>= 1) {
                    u64 o = __shfl_xor_sync(0xffffffffu, key, j);
                    bool take_max = (((lane & j) != 0) ^ ((lane & k) != 0));
                    key = take_max ? (key > o ? key : o) : (key < o ? key : o);
                }
            }
            // ascending: top-8 at lanes 24..31
            if (lane >= 32 - KSEL) {
                unsigned fb = (unsigned)(key >> 12);
                float val = funflip(fb);
                int idx = 4095 - (int)(key & 0xfffu);
                int rank = 0;
#pragma unroll
                for (int j = 24; j < 32; j++) {
                    int oi = __shfl_sync(0xffffffffu, idx, j);
                    rank += (oi < idx);
                }
                out[orow * KSEL + rank] = val;
            }
        } else {
            // SLOW PATH (rare): 8 rounds of warp-wide argmax.
            u64 mykey = 0ull;
#pragma unroll 1
            for (int k = 0; k < KSEL; k++) {
                u64 best = 0ull; int bpos = -1;
                for (int p = lane; p < n; p += 32) {
                    u64 key = pool[p];
                    if (key > best) { best = key; bpos = p; }
                }
#pragma unroll
                for (int off = 16; off > 0; off >>= 1) {
                    u64 ob = __shfl_xor_sync(0xffffffffu, best, off);
                    int op = __shfl_xor_sync(0xffffffffu, bpos, off);
                    if (ob > best) { best = ob; bpos = op; }
                }
                if (lane == k) mykey = best;
                if (lane == 0) pool[bpos] = 0ull;
                __syncwarp();
            }
            if (lane < KSEL) {
                unsigned fb = (unsigned)(mykey >> 12);
                float val = funflip(fb);
                int idx = 4095 - (int)(mykey & 0xfffu);
                int rank = 0;
#pragma unroll
                for (int j = 0; j < KSEL; j++) {
                    int oi = __shfl_sync(0xffu, idx, j);
                    rank += (oi < idx);
                }
                out[orow * KSEL + rank] = val;
            }
        }
    }
}

extern "C" void kernel_launch(void* const* d_in, const int* in_sizes, int n_in,
                              void* d_out, int out_size) {
    const float* in = (const float*)d_in[0];
    float* out = (float*)d_out;
    int rows = in_sizes[0] / ROWLEN;    // B*C = 16384 (even)
    kmax_kernel<<<rows / 2, NTHREADS>>>(in, out);
}